// round 4
// baseline (speedup 1.0000x reference)
#include <cuda_runtime.h>

#define NN    4096
#define SPLIT 32
#define TPB   256
#define RPB   (TPB / SPLIT)   // rows per block = 8

#define PED_SPEED   1.5f
#define ROBOT_SPEED 1.5f
#define K_ATTR      2.0f
#define ALPHA       10.0f
#define PED_RADIUS  0.3f
#define PED_MASS    60.0f
#define BETTA       0.71f
#define DT          0.4f
#define A_COST      4.0f
#define B_COST      1.2f
#define E_COST      0.001f
#define EPSF        1e-8f
#define LOG2E       1.4426950408889634f

__device__ __forceinline__ float ex2_approx(float x) {
    float r;
    asm("ex2.approx.ftz.f32 %0, %1;" : "=f"(r) : "f"(x));
    return r;
}

// Fused: N^2 forces + pose propagation + redundant per-block row-0 pose
// (for cost) + cost + stacked copy. 512 blocks x 256 threads; one full warp
// (32 lanes) cooperates per row -> ~28 warps/SM to cover MUFU/LDS latency.
__global__ void __launch_bounds__(256) fused_kernel(
    const float4* __restrict__ state,      // (N,4): x,y,vx,vy
    const float*  __restrict__ cost_in,    // (N)
    const float4* __restrict__ stacked_in, // (N,4)
    const float2* __restrict__ goals,      // (N,2)
    const float*  __restrict__ robot_init, // (2)
    float4* __restrict__ out_state,
    float*  __restrict__ out_cost,
    float4* __restrict__ out_stacked)
{
    __shared__ float2 sneg[NN];          // negated positions (32 KB)
    __shared__ float2 wsum[TPB / 32];    // row-0 block reduction
    __shared__ float  robo[3];           // r0x, r0y, PG

    const int tid = threadIdx.x;
    const int b   = blockIdx.x;

    // Stacked output copy for this block's 8 rows (2 x 8 float4)
    if (tid < RPB) {
        int r = b * RPB + tid;
        out_stacked[r] = stacked_in[r];
    } else if (tid < 2 * RPB) {
        int r = b * RPB + (tid - RPB);
        out_stacked[NN + r] = state[r];
    }

    // Cache NEGATED positions so diff = p + (-q) is one packed add
    #pragma unroll 4
    for (int j = tid; j < NN; j += TPB) {
        float4 s = state[j];
        sneg[j] = make_float2(-s.x, -s.y);
    }
    __syncthreads();

    const int row  = b * RPB + (tid >> 5);
    const int lane = tid & 31;

    const float4 st = state[row];  // broadcast within warp

    const float C1 = -LOG2E / BETTA;
    const float C0 = (2.0f * PED_RADIUS) * LOG2E / BETTA;

    unsigned long long p64, acc;
    asm("mov.b64 %0, {%1,%2};" : "=l"(p64) : "f"(st.x), "f"(st.y));
    asm("mov.b64 %0, {%1,%1};" : "=l"(acc) : "f"(0.0f));

    const unsigned long long* __restrict__ sq =
        reinterpret_cast<const unsigned long long*>(sneg);

    // Main N^2 loop: 128 iters/thread. Self-pair contributes exactly 0
    // (dx=dy=0, f finite via EPS) -> no mask needed.
    #pragma unroll 8
    for (int j = lane; j < NN; j += SPLIT) {
        unsigned long long q64 = sq[j];                 // LDS.64, conflict-free
        unsigned long long diff, f2;
        float dx, dy;
        asm("add.rn.f32x2 %0, %1, %2;" : "=l"(diff) : "l"(p64), "l"(q64));
        asm("mov.b64 {%0,%1}, %2;" : "=f"(dx), "=f"(dy) : "l"(diff));
        float s2  = fmaf(dx, dx, fmaf(dy, dy, EPSF));
        float rin = rsqrtf(s2);
        float d   = s2 * rin;
        float m   = ex2_approx(fmaf(d, C1, C0));
        float f   = m * rin;
        asm("mov.b64 %0, {%1,%1};" : "=l"(f2) : "f"(f));
        asm("fma.rn.f32x2 %0, %1, %2, %3;" : "=l"(acc) : "l"(f2), "l"(diff), "l"(acc));
    }

    float fx, fy;
    asm("mov.b64 {%0,%1}, %2;" : "=f"(fx), "=f"(fy) : "l"(acc));
    #pragma unroll
    for (int sh = 16; sh > 0; sh >>= 1) {
        fx += __shfl_xor_sync(0xffffffffu, fx, sh);
        fy += __shfl_xor_sync(0xffffffffu, fy, sh);
    }

    // Lane 0: attraction + pose propagation for own row
    float pnx = 0.0f, pny = 0.0f;
    if (lane == 0) {
        fx *= ALPHA;
        fy *= ALPHA;

        float2 g   = goals[row];
        float tgx  = g.x - st.x;
        float tgy  = g.y - st.y;
        float dist = sqrtf(fmaf(tgx, tgx, tgy * tgy));
        float einv = 1.0f / (dist + EPSF);
        float ds   = (row == 0) ? ROBOT_SPEED : PED_SPEED;
        float Fx   = fx + K_ATTR * (ds * tgx * einv - st.z) * PED_MASS;
        float Fy   = fy + K_ATTR * (ds * tgy * einv - st.w) * PED_MASS;

        float vnx   = fmaf(Fx, DT / PED_MASS, st.z);
        float vny   = fmaf(Fy, DT / PED_MASS, st.w);
        float speed = sqrtf(fmaf(vnx, vnx, vny * vny));
        float sc    = fminf(1.0f, PED_SPEED / (speed + EPSF));
        vnx *= sc;
        vny *= sc;
        pnx = fmaf(vnx, DT, st.x);
        pny = fmaf(vny, DT, st.y);
        out_state[row] = make_float4(pnx, pny, vnx, vny);
    }

    // ---- Redundant row-0 force (16 iters/thread) for this block's cost ----
    const float4 s0 = state[0];
    float f0x = 0.0f, f0y = 0.0f;
    #pragma unroll
    for (int k = 0; k < NN / TPB; k++) {
        float2 nq = sneg[tid + k * TPB];
        float dx  = s0.x + nq.x;
        float dy  = s0.y + nq.y;
        float s2  = fmaf(dx, dx, fmaf(dy, dy, EPSF));
        float rin = rsqrtf(s2);
        float d   = s2 * rin;
        float mm  = ex2_approx(fmaf(d, C1, C0));
        float f   = mm * rin;
        f0x = fmaf(f, dx, f0x);
        f0y = fmaf(f, dy, f0y);
    }
    #pragma unroll
    for (int sh = 16; sh > 0; sh >>= 1) {
        f0x += __shfl_xor_sync(0xffffffffu, f0x, sh);
        f0y += __shfl_xor_sync(0xffffffffu, f0y, sh);
    }
    if ((tid & 31) == 0) wsum[tid >> 5] = make_float2(f0x, f0y);
    __syncthreads();

    if (tid == 0) {
        float rx = 0.0f, ry = 0.0f;
        #pragma unroll
        for (int w = 0; w < TPB / 32; w++) { rx += wsum[w].x; ry += wsum[w].y; }
        rx *= ALPHA;
        ry *= ALPHA;

        float2 g0  = goals[0];
        float tgx  = g0.x - s0.x;
        float tgy  = g0.y - s0.y;
        float dist = sqrtf(fmaf(tgx, tgx, tgy * tgy));
        float einv = 1.0f / (dist + EPSF);
        float Fx   = rx + K_ATTR * (ROBOT_SPEED * tgx * einv - s0.z) * PED_MASS;
        float Fy   = ry + K_ATTR * (ROBOT_SPEED * tgy * einv - s0.w) * PED_MASS;

        float vnx   = fmaf(Fx, DT / PED_MASS, s0.z);
        float vny   = fmaf(Fy, DT / PED_MASS, s0.w);
        float speed = sqrtf(fmaf(vnx, vnx, vny * vny));
        float sc    = fminf(1.0f, PED_SPEED / (speed + EPSF));
        vnx *= sc;
        vny *= sc;
        float r0x = fmaf(vnx, DT, s0.x);
        float r0y = fmaf(vny, DT, s0.y);

        float rix = robot_init[0];
        float riy = robot_init[1];
        float gx  = g0.x - rix;
        float gy  = g0.y - riy;
        float PG  = (gx * (r0x - rix) + gy * (r0y - riy)) /
                    (sqrtf(fmaf(gx, gx, gy * gy)) + E_COST);
        robo[0] = r0x;
        robo[1] = r0y;
        robo[2] = PG;
    }
    __syncthreads();

    // Lane 0: cost for own row
    if (lane == 0) {
        float r0x = robo[0], r0y = robo[1], PG = robo[2];
        float ddx = pnx - r0x;
        float ddy = pny - r0y;
        float dr  = sqrtf(fmaf(ddx, ddx, fmaf(ddy, ddy, E_COST)));
        float blame = (row == 0) ? 0.0f : ex2_approx(-dr * (LOG2E / B_COST));
        out_cost[row] = cost_in[row] + (-A_COST * PG + blame);
    }
}

extern "C" void kernel_launch(void* const* d_in, const int* in_sizes, int n_in,
                              void* d_out, int out_size)
{
    const float4* state   = (const float4*)d_in[0];
    const float*  cost    = (const float*)d_in[1];
    const float4* stacked = (const float4*)d_in[2];
    const float2* goals   = (const float2*)d_in[3];
    const float*  rinit   = (const float*)d_in[4];

    float*  out         = (float*)d_out;
    float4* out_state   = (float4*)out;            // [0, 4N)
    float*  out_cost    = out + 4 * NN;            // [4N, 5N)
    float4* out_stacked = (float4*)(out + 5 * NN); // [5N, 13N)

    fused_kernel<<<NN / RPB, TPB>>>(state, cost, stacked, goals, rinit,
                                    out_state, out_cost, out_stacked);
}

// round 5
// speedup vs baseline: 1.0100x; 1.0100x over previous
#include <cuda_runtime.h>

#define NN    4096
#define SPLIT 32
#define TPB   512
#define RPB   (TPB / SPLIT)   // rows per block = 16
#define NWARP (TPB / 32)

#define PED_SPEED   1.5f
#define ROBOT_SPEED 1.5f
#define K_ATTR      2.0f
#define ALPHA       10.0f
#define PED_RADIUS  0.3f
#define PED_MASS    60.0f
#define BETTA       0.71f
#define DT          0.4f
#define A_COST      4.0f
#define B_COST      1.2f
#define E_COST      0.001f
#define EPSF        1e-8f
#define LOG2E       1.4426950408889634f

__device__ __forceinline__ float ex2_approx(float x) {
    float r;
    asm("ex2.approx.ftz.f32 %0, %1;" : "=f"(r) : "f"(x));
    return r;
}

// Fused: N^2 forces + pose propagation + per-block redundant row-0 pose
// (for cost) + cost + stacked copy. 256 blocks x 512 threads; one warp per
// row. Scalar inner loop (12 instrs/iter), MUFU floor 16 cyc/iter.
__global__ void __launch_bounds__(512) fused_kernel(
    const float4* __restrict__ state,      // (N,4): x,y,vx,vy
    const float*  __restrict__ cost_in,    // (N)
    const float4* __restrict__ stacked_in, // (N,4)
    const float2* __restrict__ goals,      // (N,2)
    const float*  __restrict__ robot_init, // (2)
    float4* __restrict__ out_state,
    float*  __restrict__ out_cost,
    float4* __restrict__ out_stacked)
{
    __shared__ float2 spos[NN];          // positions (32 KB)
    __shared__ float2 wsum[NWARP];       // row-0 block reduction
    __shared__ float  robo[3];           // r0x, r0y, PG

    const int tid = threadIdx.x;
    const int b   = blockIdx.x;

    // Stacked output copy for this block's 16 rows (2 x 16 float4)
    if (tid < RPB) {
        int r = b * RPB + tid;
        out_stacked[r] = stacked_in[r];
    } else if (tid < 2 * RPB) {
        int r = b * RPB + (tid - RPB);
        out_stacked[NN + r] = state[r];
    }

    // Cache positions (8 iters/thread)
    #pragma unroll
    for (int k = 0; k < NN / TPB; k++) {
        int j = tid + k * TPB;
        float4 s = state[j];
        spos[j] = make_float2(s.x, s.y);
    }
    __syncthreads();

    const int row  = b * RPB + (tid >> 5);
    const int lane = tid & 31;

    const float4 st = state[row];  // broadcast within warp
    const float px = st.x, py = st.y;

    const float C1 = -LOG2E / BETTA;
    const float C0 = (2.0f * PED_RADIUS) * LOG2E / BETTA;

    float fx = 0.0f, fy = 0.0f;

    // Main N^2 loop: 128 iters/thread. Self-pair contributes exactly 0
    // (dx=dy=0, f finite via EPS) -> no mask needed.
    #pragma unroll 8
    for (int j = lane; j < NN; j += SPLIT) {
        float2 q  = spos[j];                 // LDS.64, conflict-free
        float dx  = px - q.x;
        float dy  = py - q.y;
        float s2  = fmaf(dx, dx, fmaf(dy, dy, EPSF));
        float rin = rsqrtf(s2);
        float d   = s2 * rin;
        float m   = ex2_approx(fmaf(d, C1, C0));
        float f   = m * rin;
        fx = fmaf(f, dx, fx);
        fy = fmaf(f, dy, fy);
    }

    #pragma unroll
    for (int sh = 16; sh > 0; sh >>= 1) {
        fx += __shfl_xor_sync(0xffffffffu, fx, sh);
        fy += __shfl_xor_sync(0xffffffffu, fy, sh);
    }

    // Lane 0: attraction + pose propagation for own row
    float pnx = 0.0f, pny = 0.0f;
    if (lane == 0) {
        fx *= ALPHA;
        fy *= ALPHA;

        float2 g   = goals[row];
        float tgx  = g.x - px;
        float tgy  = g.y - py;
        float dist = sqrtf(fmaf(tgx, tgx, tgy * tgy));
        float einv = 1.0f / (dist + EPSF);
        float ds   = (row == 0) ? ROBOT_SPEED : PED_SPEED;
        float Fx   = fx + K_ATTR * (ds * tgx * einv - st.z) * PED_MASS;
        float Fy   = fy + K_ATTR * (ds * tgy * einv - st.w) * PED_MASS;

        float vnx   = fmaf(Fx, DT / PED_MASS, st.z);
        float vny   = fmaf(Fy, DT / PED_MASS, st.w);
        float speed = sqrtf(fmaf(vnx, vnx, vny * vny));
        float sc    = fminf(1.0f, PED_SPEED / (speed + EPSF));
        vnx *= sc;
        vny *= sc;
        pnx = fmaf(vnx, DT, px);
        pny = fmaf(vny, DT, py);
        out_state[row] = make_float4(pnx, pny, vnx, vny);
    }

    // ---- Redundant row-0 force (8 iters/thread) for this block's cost ----
    const float4 s0 = state[0];
    float f0x = 0.0f, f0y = 0.0f;
    #pragma unroll
    for (int k = 0; k < NN / TPB; k++) {
        float2 q  = spos[tid + k * TPB];
        float dx  = s0.x - q.x;
        float dy  = s0.y - q.y;
        float s2  = fmaf(dx, dx, fmaf(dy, dy, EPSF));
        float rin = rsqrtf(s2);
        float d   = s2 * rin;
        float mm  = ex2_approx(fmaf(d, C1, C0));
        float f   = mm * rin;
        f0x = fmaf(f, dx, f0x);
        f0y = fmaf(f, dy, f0y);
    }
    #pragma unroll
    for (int sh = 16; sh > 0; sh >>= 1) {
        f0x += __shfl_xor_sync(0xffffffffu, f0x, sh);
        f0y += __shfl_xor_sync(0xffffffffu, f0y, sh);
    }
    if ((tid & 31) == 0) wsum[tid >> 5] = make_float2(f0x, f0y);
    __syncthreads();

    if (tid == 0) {
        float rx = 0.0f, ry = 0.0f;
        #pragma unroll
        for (int w = 0; w < NWARP; w++) { rx += wsum[w].x; ry += wsum[w].y; }
        rx *= ALPHA;
        ry *= ALPHA;

        float2 g0  = goals[0];
        float tgx  = g0.x - s0.x;
        float tgy  = g0.y - s0.y;
        float dist = sqrtf(fmaf(tgx, tgx, tgy * tgy));
        float einv = 1.0f / (dist + EPSF);
        float Fx   = rx + K_ATTR * (ROBOT_SPEED * tgx * einv - s0.z) * PED_MASS;
        float Fy   = ry + K_ATTR * (ROBOT_SPEED * tgy * einv - s0.w) * PED_MASS;

        float vnx   = fmaf(Fx, DT / PED_MASS, s0.z);
        float vny   = fmaf(Fy, DT / PED_MASS, s0.w);
        float speed = sqrtf(fmaf(vnx, vnx, vny * vny));
        float sc    = fminf(1.0f, PED_SPEED / (speed + EPSF));
        vnx *= sc;
        vny *= sc;
        float r0x = fmaf(vnx, DT, s0.x);
        float r0y = fmaf(vny, DT, s0.y);

        float rix = robot_init[0];
        float riy = robot_init[1];
        float gx  = g0.x - rix;
        float gy  = g0.y - riy;
        float PG  = (gx * (r0x - rix) + gy * (r0y - riy)) /
                    (sqrtf(fmaf(gx, gx, gy * gy)) + E_COST);
        robo[0] = r0x;
        robo[1] = r0y;
        robo[2] = PG;
    }
    __syncthreads();

    // Lane 0: cost for own row
    if (lane == 0) {
        float r0x = robo[0], r0y = robo[1], PG = robo[2];
        float ddx = pnx - r0x;
        float ddy = pny - r0y;
        float dr  = sqrtf(fmaf(ddx, ddx, fmaf(ddy, ddy, E_COST)));
        float blame = (row == 0) ? 0.0f : ex2_approx(-dr * (LOG2E / B_COST));
        out_cost[row] = cost_in[row] + (-A_COST * PG + blame);
    }
}

extern "C" void kernel_launch(void* const* d_in, const int* in_sizes, int n_in,
                              void* d_out, int out_size)
{
    const float4* state   = (const float4*)d_in[0];
    const float*  cost    = (const float*)d_in[1];
    const float4* stacked = (const float4*)d_in[2];
    const float2* goals   = (const float2*)d_in[3];
    const float*  rinit   = (const float*)d_in[4];

    float*  out         = (float*)d_out;
    float4* out_state   = (float4*)out;            // [0, 4N)
    float*  out_cost    = out + 4 * NN;            // [4N, 5N)
    float4* out_stacked = (float4*)(out + 5 * NN); // [5N, 13N)

    fused_kernel<<<NN / RPB, TPB>>>(state, cost, stacked, goals, rinit,
                                    out_state, out_cost, out_stacked);
}

// round 6
// speedup vs baseline: 1.1480x; 1.1366x over previous
#include <cuda_runtime.h>

#define NN    4096
#define SPLIT 32
#define TPB   512
#define RPB   (TPB / SPLIT)   // rows per block = 16
#define NWARP (TPB / 32)

#define PED_SPEED   1.5f
#define ROBOT_SPEED 1.5f
#define K_ATTR      2.0f
#define ALPHA       10.0f
#define PED_RADIUS  0.3f
#define PED_MASS    60.0f
#define BETTA       0.71f
#define DT          0.4f
#define A_COST      4.0f
#define B_COST      1.2f
#define E_COST      0.001f
#define EPSF        1e-8f
#define LOG2E       1.4426950408889634f

__device__ __forceinline__ float ex2_approx(float x) {
    float r;
    asm("ex2.approx.ftz.f32 %0, %1;" : "=f"(r) : "f"(x));
    return r;
}
__device__ __forceinline__ float rsqrt_approx(float x) {
    float r;
    asm("rsqrt.approx.ftz.f32 %0, %1;" : "=f"(r) : "f"(x));
    return r;
}

// Fused: N^2 forces + pose propagation + per-block redundant row-0 pose
// (for cost) + cost + stacked copy. 256 blocks x 512 threads; one warp per
// row. Counted inner loop (compile-time trip count 64), 2 pairs per LDS.128.
__global__ void __launch_bounds__(512) fused_kernel(
    const float4* __restrict__ state,      // (N,4): x,y,vx,vy
    const float*  __restrict__ cost_in,    // (N)
    const float4* __restrict__ stacked_in, // (N,4)
    const float2* __restrict__ goals,      // (N,2)
    const float*  __restrict__ robot_init, // (2)
    float4* __restrict__ out_state,
    float*  __restrict__ out_cost,
    float4* __restrict__ out_stacked)
{
    __shared__ float2 spos[NN];          // positions (32 KB)
    __shared__ float2 wsum[NWARP];       // row-0 block reduction
    __shared__ float  robo[3];           // r0x, r0y, PG

    const int tid = threadIdx.x;
    const int b   = blockIdx.x;

    // Stacked output copy for this block's 16 rows (2 x 16 float4)
    if (tid < RPB) {
        int r = b * RPB + tid;
        out_stacked[r] = stacked_in[r];
    } else if (tid < 2 * RPB) {
        int r = b * RPB + (tid - RPB);
        out_stacked[NN + r] = state[r];
    }

    // Cache positions (8 iters/thread, counted loop)
    #pragma unroll
    for (int k = 0; k < NN / TPB; k++) {
        int j = tid + k * TPB;
        float4 s = state[j];
        spos[j] = make_float2(s.x, s.y);
    }
    __syncthreads();

    const int row  = b * RPB + (tid >> 5);
    const int lane = tid & 31;

    const float4 st = state[row];  // broadcast within warp
    const float px = st.x, py = st.y;

    const float C1 = -LOG2E / BETTA;
    const float C0 = (2.0f * PED_RADIUS) * LOG2E / BETTA;

    float fxa = 0.0f, fya = 0.0f;  // two independent accumulator chains
    float fxb = 0.0f, fyb = 0.0f;

    // Main N^2 loop: 64 counted iterations, 2 pairs per LDS.128.
    // Self-pair contributes exactly 0 (dx=dy=0, f finite via EPS) -> no mask.
    const float4* __restrict__ sq4 = reinterpret_cast<const float4*>(spos);
    #pragma unroll 8
    for (int k = 0; k < NN / SPLIT / 2; k++) {        // 64 iters
        float4 q = sq4[lane + k * SPLIT];             // pairs 2i, 2i+1

        float dx0  = px - q.x;
        float dy0  = py - q.y;
        float s20  = fmaf(dx0, dx0, fmaf(dy0, dy0, EPSF));
        float rin0 = rsqrt_approx(s20);
        float m0   = ex2_approx(fmaf(s20 * rin0, C1, C0));
        float f0   = m0 * rin0;
        fxa = fmaf(f0, dx0, fxa);
        fya = fmaf(f0, dy0, fya);

        float dx1  = px - q.z;
        float dy1  = py - q.w;
        float s21  = fmaf(dx1, dx1, fmaf(dy1, dy1, EPSF));
        float rin1 = rsqrt_approx(s21);
        float m1   = ex2_approx(fmaf(s21 * rin1, C1, C0));
        float f1   = m1 * rin1;
        fxb = fmaf(f1, dx1, fxb);
        fyb = fmaf(f1, dy1, fyb);
    }
    float fx = fxa + fxb;
    float fy = fya + fyb;

    #pragma unroll
    for (int sh = 16; sh > 0; sh >>= 1) {
        fx += __shfl_xor_sync(0xffffffffu, fx, sh);
        fy += __shfl_xor_sync(0xffffffffu, fy, sh);
    }

    // Lane 0: attraction + pose propagation for own row
    float pnx = 0.0f, pny = 0.0f;
    if (lane == 0) {
        fx *= ALPHA;
        fy *= ALPHA;

        float2 g   = goals[row];
        float tgx  = g.x - px;
        float tgy  = g.y - py;
        float dist = sqrtf(fmaf(tgx, tgx, tgy * tgy));
        float einv = 1.0f / (dist + EPSF);
        float ds   = (row == 0) ? ROBOT_SPEED : PED_SPEED;
        float Fx   = fx + K_ATTR * (ds * tgx * einv - st.z) * PED_MASS;
        float Fy   = fy + K_ATTR * (ds * tgy * einv - st.w) * PED_MASS;

        float vnx   = fmaf(Fx, DT / PED_MASS, st.z);
        float vny   = fmaf(Fy, DT / PED_MASS, st.w);
        float speed = sqrtf(fmaf(vnx, vnx, vny * vny));
        float sc    = fminf(1.0f, PED_SPEED / (speed + EPSF));
        vnx *= sc;
        vny *= sc;
        pnx = fmaf(vnx, DT, px);
        pny = fmaf(vny, DT, py);
        out_state[row] = make_float4(pnx, pny, vnx, vny);
    }

    // ---- Redundant row-0 force (4 counted iters, 2 pairs each) ----
    const float4 s0 = state[0];
    float f0x = 0.0f, f0y = 0.0f;
    #pragma unroll
    for (int k = 0; k < NN / TPB / 2; k++) {          // 4 iters
        float4 q = sq4[tid + k * TPB];

        float dx0  = s0.x - q.x;
        float dy0  = s0.y - q.y;
        float s20  = fmaf(dx0, dx0, fmaf(dy0, dy0, EPSF));
        float rin0 = rsqrt_approx(s20);
        float m0   = ex2_approx(fmaf(s20 * rin0, C1, C0));
        float ff0  = m0 * rin0;
        f0x = fmaf(ff0, dx0, f0x);
        f0y = fmaf(ff0, dy0, f0y);

        float dx1  = s0.x - q.z;
        float dy1  = s0.y - q.w;
        float s21  = fmaf(dx1, dx1, fmaf(dy1, dy1, EPSF));
        float rin1 = rsqrt_approx(s21);
        float m1   = ex2_approx(fmaf(s21 * rin1, C1, C0));
        float ff1  = m1 * rin1;
        f0x = fmaf(ff1, dx1, f0x);
        f0y = fmaf(ff1, dy1, f0y);
    }
    #pragma unroll
    for (int sh = 16; sh > 0; sh >>= 1) {
        f0x += __shfl_xor_sync(0xffffffffu, f0x, sh);
        f0y += __shfl_xor_sync(0xffffffffu, f0y, sh);
    }
    if ((tid & 31) == 0) wsum[tid >> 5] = make_float2(f0x, f0y);
    __syncthreads();

    if (tid == 0) {
        float rx = 0.0f, ry = 0.0f;
        #pragma unroll
        for (int w = 0; w < NWARP; w++) { rx += wsum[w].x; ry += wsum[w].y; }
        rx *= ALPHA;
        ry *= ALPHA;

        float2 g0  = goals[0];
        float tgx  = g0.x - s0.x;
        float tgy  = g0.y - s0.y;
        float dist = sqrtf(fmaf(tgx, tgx, tgy * tgy));
        float einv = 1.0f / (dist + EPSF);
        float Fx   = rx + K_ATTR * (ROBOT_SPEED * tgx * einv - s0.z) * PED_MASS;
        float Fy   = ry + K_ATTR * (ROBOT_SPEED * tgy * einv - s0.w) * PED_MASS;

        float vnx   = fmaf(Fx, DT / PED_MASS, s0.z);
        float vny   = fmaf(Fy, DT / PED_MASS, s0.w);
        float speed = sqrtf(fmaf(vnx, vnx, vny * vny));
        float sc    = fminf(1.0f, PED_SPEED / (speed + EPSF));
        vnx *= sc;
        vny *= sc;
        float r0x = fmaf(vnx, DT, s0.x);
        float r0y = fmaf(vny, DT, s0.y);

        float rix = robot_init[0];
        float riy = robot_init[1];
        float gx  = g0.x - rix;
        float gy  = g0.y - riy;
        float PG  = (gx * (r0x - rix) + gy * (r0y - riy)) /
                    (sqrtf(fmaf(gx, gx, gy * gy)) + E_COST);
        robo[0] = r0x;
        robo[1] = r0y;
        robo[2] = PG;
    }
    __syncthreads();

    // Lane 0: cost for own row
    if (lane == 0) {
        float r0x = robo[0], r0y = robo[1], PG = robo[2];
        float ddx = pnx - r0x;
        float ddy = pny - r0y;
        float dr  = sqrtf(fmaf(ddx, ddx, fmaf(ddy, ddy, E_COST)));
        float blame = (row == 0) ? 0.0f : ex2_approx(-dr * (LOG2E / B_COST));
        out_cost[row] = cost_in[row] + (-A_COST * PG + blame);
    }
}

extern "C" void kernel_launch(void* const* d_in, const int* in_sizes, int n_in,
                              void* d_out, int out_size)
{
    const float4* state   = (const float4*)d_in[0];
    const float*  cost    = (const float*)d_in[1];
    const float4* stacked = (const float4*)d_in[2];
    const float2* goals   = (const float2*)d_in[3];
    const float*  rinit   = (const float*)d_in[4];

    float*  out         = (float*)d_out;
    float4* out_state   = (float4*)out;            // [0, 4N)
    float*  out_cost    = out + 4 * NN;            // [4N, 5N)
    float4* out_stacked = (float4*)(out + 5 * NN); // [5N, 13N)

    fused_kernel<<<NN / RPB, TPB>>>(state, cost, stacked, goals, rinit,
                                    out_state, out_cost, out_stacked);
}